// round 1
// baseline (speedup 1.0000x reference)
#include <cuda_runtime.h>

#define BB 8
#define LL 1024
#define SSq 1024
#define HH 12
#define EE 64
#define DD 64

#define LT 32            // L rows per CTA
#define ST 64            // S tile (K/V rows per stage)
#define NTHREADS 256

// smem strides (floats)
#define QSTR 68
#define KSTR 68
#define PSTR 1028

#define SMEM_FLOATS (LT*QSTR + ST*KSTR + LT*PSTR)
#define SMEM_BYTES  (SMEM_FLOATS * 4)

// fast exp(x) for x <= 0 (x = score - rowmax). ~3e-6 rel err, no MUFU.
__device__ __forceinline__ float fast_exp(float x) {
    float t = fmaxf(x * 1.4426950408889634f, -126.0f);   // log2(e)
    float nf = t + 12582912.0f;                          // round-to-nearest magic (1.5*2^23)
    float f  = t - (nf - 12582912.0f);                   // f in [-0.5, 0.5]
    int   ni = __float_as_int(nf) - 0x4B400000;
    // 2^f Taylor (deg 5): max rel err ~2.4e-6 on [-0.5,0.5]
    float p = 0.0013333558146428443f;
    p = fmaf(p, f, 0.009618129107628477f);
    p = fmaf(p, f, 0.05550410866482158f);
    p = fmaf(p, f, 0.2402265069591007f);
    p = fmaf(p, f, 0.6931471805599453f);
    p = fmaf(p, f, 1.0f);
    return __int_as_float((ni + 127) << 23) * p;
}

__global__ void __launch_bounds__(NTHREADS, 1)
lsa_attn_kernel(const float* __restrict__ q, const float* __restrict__ k,
                const float* __restrict__ v, const float* __restrict__ scale,
                float* __restrict__ out)
{
    extern __shared__ float sm[];
    float* sQ  = sm;                        // [LT][QSTR]
    float* sKV = sm + LT*QSTR;              // [ST][KSTR]
    float* sP  = sm + LT*QSTR + ST*KSTR;    // [LT][PSTR]
    __shared__ float sRinv[LT];

    const int tid   = threadIdx.x;
    const int bid   = blockIdx.x;
    const int ltile = bid & 31;             // L/LT = 32 tiles
    const int h     = (bid >> 5) % HH;
    const int b     = bid / (32 * HH);
    const int row0  = ltile * LT;

    const float sc = __ldg(scale + h);

    const float* Qp = q + (((size_t)b * LL + row0) * HH + h) * EE;
    const float* Kp = k + ((size_t)b * SSq * HH + h) * EE;   // row s: + s*HH*EE
    const float* Vp = v + ((size_t)b * SSq * HH + h) * DD;
    float* Vout = out + (((size_t)b * LL + row0) * HH + h) * DD;
    float* Aout = out + (size_t)BB * LL * HH * DD
                      + (((size_t)b * HH + h) * LL + row0) * (size_t)SSq;

    // ---- load Q tile, pre-scaled by per-head scale ----
    for (int i = tid; i < LT * EE / 4; i += NTHREADS) {
        int r = i >> 4, c4 = i & 15;
        float4 t = *reinterpret_cast<const float4*>(Qp + (size_t)r * HH * EE + c4 * 4);
        t.x *= sc; t.y *= sc; t.z *= sc; t.w *= sc;
        *reinterpret_cast<float4*>(sQ + r * QSTR + c4 * 4) = t;
    }

    const int rowg = tid >> 4;   // 0..15 (2 rows each)
    const int colg = tid & 15;   // 0..15 (4 cols each)
    const int r0t  = rowg * 2;
    const int c0t  = colg * 4;

    // ================= Phase 1: scores = (Q*scale) . K^T =================
    for (int st = 0; st < SSq / ST; ++st) {
        __syncthreads();
        for (int i = tid; i < ST * EE / 4; i += NTHREADS) {
            int s = i >> 4, c4 = i & 15;
            *reinterpret_cast<float4*>(sKV + s * KSTR + c4 * 4) =
                *reinterpret_cast<const float4*>(Kp + (size_t)(st * ST + s) * HH * EE + c4 * 4);
        }
        __syncthreads();

        float acc[2][4] = {};
        #pragma unroll
        for (int e4 = 0; e4 < EE / 4; ++e4) {
            float4 q0 = *reinterpret_cast<const float4*>(sQ + (r0t + 0) * QSTR + e4 * 4);
            float4 q1 = *reinterpret_cast<const float4*>(sQ + (r0t + 1) * QSTR + e4 * 4);
            #pragma unroll
            for (int jj = 0; jj < 4; ++jj) {
                float4 kv = *reinterpret_cast<const float4*>(sKV + (c0t + jj) * KSTR + e4 * 4);
                acc[0][jj] = fmaf(q0.x, kv.x, acc[0][jj]);
                acc[0][jj] = fmaf(q0.y, kv.y, acc[0][jj]);
                acc[0][jj] = fmaf(q0.z, kv.z, acc[0][jj]);
                acc[0][jj] = fmaf(q0.w, kv.w, acc[0][jj]);
                acc[1][jj] = fmaf(q1.x, kv.x, acc[1][jj]);
                acc[1][jj] = fmaf(q1.y, kv.y, acc[1][jj]);
                acc[1][jj] = fmaf(q1.z, kv.z, acc[1][jj]);
                acc[1][jj] = fmaf(q1.w, kv.w, acc[1][jj]);
            }
        }
        #pragma unroll
        for (int j = 0; j < 2; ++j) {
            float4 t = make_float4(acc[j][0], acc[j][1], acc[j][2], acc[j][3]);
            *reinterpret_cast<float4*>(sP + (r0t + j) * PSTR + st * ST + c0t) = t;
        }
    }
    __syncthreads();

    // ================= Phase 2: softmax (write A) =================
    {
        const int lane = tid & 31, wid = tid >> 5;   // 8 warps x 4 rows
        #pragma unroll
        for (int rr = 0; rr < 4; ++rr) {
            int r = wid * 4 + rr;
            int grow = row0 + r;
            float* rowp = sP + r * PSTR;

            float m = -3.4e38f;
            #pragma unroll
            for (int i = 0; i < 8; ++i) {
                float4 t = *reinterpret_cast<const float4*>(rowp + (lane + i * 32) * 4);
                m = fmaxf(m, fmaxf(fmaxf(t.x, t.y), fmaxf(t.z, t.w)));
            }
            #pragma unroll
            for (int o = 16; o; o >>= 1) m = fmaxf(m, __shfl_xor_sync(0xffffffffu, m, o));

            float sum = 0.f;
            #pragma unroll
            for (int i = 0; i < 8; ++i) {
                int c = (lane + i * 32) * 4;
                float4 t = *reinterpret_cast<const float4*>(rowp + c);
                float4 p;
                p.x = fast_exp(t.x - m);
                p.y = fast_exp(t.y - m);
                p.z = fast_exp(t.z - m);
                p.w = fast_exp(t.w - m);
                p.x = (c + 0 == grow) ? 0.f : p.x;   // LSA diagonal self-mask
                p.y = (c + 1 == grow) ? 0.f : p.y;
                p.z = (c + 2 == grow) ? 0.f : p.z;
                p.w = (c + 3 == grow) ? 0.f : p.w;
                *reinterpret_cast<float4*>(rowp + c) = p;
                sum += (p.x + p.y) + (p.z + p.w);
            }
            #pragma unroll
            for (int o = 16; o; o >>= 1) sum += __shfl_xor_sync(0xffffffffu, sum, o);
            float rinv = 1.0f / sum;
            if (lane == 0) sRinv[r] = rinv;

            float* arow = Aout + (size_t)r * SSq;
            #pragma unroll
            for (int i = 0; i < 8; ++i) {
                int c = (lane + i * 32) * 4;
                float4 t = *reinterpret_cast<const float4*>(rowp + c);
                t.x *= rinv; t.y *= rinv; t.z *= rinv; t.w *= rinv;
                *reinterpret_cast<float4*>(arow + c) = t;
            }
        }
    }

    // ================= Phase 3: V = P . values (then * rinv) =================
    float acc[2][4] = {};
    for (int vt = 0; vt < SSq / ST; ++vt) {
        __syncthreads();
        for (int i = tid; i < ST * DD / 4; i += NTHREADS) {
            int s = i >> 4, c4 = i & 15;
            *reinterpret_cast<float4*>(sKV + s * KSTR + c4 * 4) =
                *reinterpret_cast<const float4*>(Vp + (size_t)(vt * ST + s) * HH * DD + c4 * 4);
        }
        __syncthreads();

        #pragma unroll
        for (int s4 = 0; s4 < ST / 4; ++s4) {
            float4 p0 = *reinterpret_cast<const float4*>(sP + (r0t + 0) * PSTR + vt * ST + s4 * 4);
            float4 p1 = *reinterpret_cast<const float4*>(sP + (r0t + 1) * PSTR + vt * ST + s4 * 4);
            const float* pp0 = &p0.x;
            const float* pp1 = &p1.x;
            #pragma unroll
            for (int u = 0; u < 4; ++u) {
                float4 vv = *reinterpret_cast<const float4*>(sKV + (s4 * 4 + u) * KSTR + c0t);
                float a0 = pp0[u], a1 = pp1[u];
                acc[0][0] = fmaf(a0, vv.x, acc[0][0]);
                acc[0][1] = fmaf(a0, vv.y, acc[0][1]);
                acc[0][2] = fmaf(a0, vv.z, acc[0][2]);
                acc[0][3] = fmaf(a0, vv.w, acc[0][3]);
                acc[1][0] = fmaf(a1, vv.x, acc[1][0]);
                acc[1][1] = fmaf(a1, vv.y, acc[1][1]);
                acc[1][2] = fmaf(a1, vv.z, acc[1][2]);
                acc[1][3] = fmaf(a1, vv.w, acc[1][3]);
            }
        }
    }

    {
        float r0v = sRinv[r0t], r1v = sRinv[r0t + 1];
        float4 o0 = make_float4(acc[0][0] * r0v, acc[0][1] * r0v, acc[0][2] * r0v, acc[0][3] * r0v);
        float4 o1 = make_float4(acc[1][0] * r1v, acc[1][1] * r1v, acc[1][2] * r1v, acc[1][3] * r1v);
        *reinterpret_cast<float4*>(Vout + (size_t)(r0t + 0) * HH * DD + c0t) = o0;
        *reinterpret_cast<float4*>(Vout + (size_t)(r0t + 1) * HH * DD + c0t) = o1;
    }
}

extern "C" void kernel_launch(void* const* d_in, const int* in_sizes, int n_in,
                              void* d_out, int out_size) {
    (void)in_sizes; (void)n_in; (void)out_size;
    const float* q     = (const float*)d_in[0];
    const float* k     = (const float*)d_in[1];
    const float* v     = (const float*)d_in[2];
    const float* scale = (const float*)d_in[3];
    float* out = (float*)d_out;

    static bool attr_set = false;
    if (!attr_set) {
        cudaFuncSetAttribute(lsa_attn_kernel,
                             cudaFuncAttributeMaxDynamicSharedMemorySize, SMEM_BYTES);
        attr_set = true;
    }

    dim3 grid(BB * HH * (LL / LT));   // 3072
    lsa_attn_kernel<<<grid, NTHREADS, SMEM_BYTES>>>(q, k, v, scale, out);
}